// round 5
// baseline (speedup 1.0000x reference)
#include <cuda_runtime.h>
#include <cstdint>

// ---------------------------------------------------------------------------
// Grouped MoE MLP, legacy tensor path (mma.sync.m16n8k8.tf32, fp32 accum).
//   GEMM1: h = swiglu(x @ W1^T + b1)   then  GEMM2: out = h @ W2^T + b2
//
// CTA tile 256x192, BK=32, 512 threads (16 warps, 4x4), warp tile 64x48,
// 3-stage cp.async pipeline, smem rows padded to LDT=36 floats so fragment
// LDS bank = (4r+c)%32 is conflict-free. CVT f32->tf32 stays in the main
// loop: with 24 mma / 80 issues per K=8 slice the kernel is HMMA-pipe bound
// and the CVTs ride in the issue slack.
// ---------------------------------------------------------------------------

#define BM 256
#define BN 192
#define BK 32
#define LDT 36
#define STAGES 3
#define STAGE_FLOATS ((BM + BN) * LDT)        // 16128 floats
#define A_FLOATS (BM * LDT)                   // 9216
#define SMEM_BYTES (STAGES * STAGE_FLOATS * 4 + BN * 4)   // 194304

#define ALPHA_SWIGLU 1.702f
#define LIMIT_SWIGLU 7.0f

// intermediate h = swiglu(gemm1) : [N, H] fp32 (16384 x 2880)
__device__ float g_h[16384ull * 2880ull];

// ----------------------------- PTX helpers ---------------------------------

__device__ __forceinline__ void cp_async16(uint32_t saddr, const void* gptr, int src_bytes) {
    asm volatile("cp.async.cg.shared.global [%0], [%1], 16, %2;\n"
                 :: "r"(saddr), "l"(gptr), "r"(src_bytes));
}
__device__ __forceinline__ void cp_commit() {
    asm volatile("cp.async.commit_group;\n" ::);
}
template <int Npend>
__device__ __forceinline__ void cp_wait() {
    asm volatile("cp.async.wait_group %0;\n" :: "n"(Npend));
}
__device__ __forceinline__ uint32_t f2tf(float x) {
    uint32_t u;
    asm("cvt.rna.tf32.f32 %0, %1;" : "=r"(u) : "f"(x));
    return u;
}
__device__ __forceinline__ void mma_tf32(float* c, const uint32_t* a, const uint32_t* b) {
    asm volatile(
        "mma.sync.aligned.m16n8k8.row.col.f32.tf32.tf32.f32 "
        "{%0,%1,%2,%3}, {%4,%5,%6,%7}, {%8,%9}, {%0,%1,%2,%3};\n"
        : "+f"(c[0]), "+f"(c[1]), "+f"(c[2]), "+f"(c[3])
        : "r"(a[0]), "r"(a[1]), "r"(a[2]), "r"(a[3]), "r"(b[0]), "r"(b[1]));
}
__device__ __forceinline__ float swiglu_pair(float glu_in, float lin_in) {
    float g = fminf(glu_in, LIMIT_SWIGLU);
    float l = fminf(fmaxf(lin_in, -LIMIT_SWIGLU), LIMIT_SWIGLU);
    float sig = 1.0f / (1.0f + __expf(-ALPHA_SWIGLU * g));
    return g * sig * (l + 1.0f);
}

// ---------------------------------------------------------------------------
// EPI=0: GEMM1 epilogue -> h[token, col/2] = swiglu(c0+b0, c1+b1)
// EPI=1: GEMM2 epilogue -> out[token, col] = c + bias
// A: [rows, K] row-major. Bw: [E, Ncols, K] (K contiguous). bias: [E, Ncols].
// ---------------------------------------------------------------------------
template <int EPI>
__global__ void __launch_bounds__(512, 1)
grouped_gemm_tf32(const float* __restrict__ A,
                  const float* __restrict__ Bw,
                  const float* __restrict__ bias,
                  const int*   __restrict__ ntpe,
                  float*       __restrict__ Cout,
                  int K, int Ncols, int E, int mtiles_per_e, int Ntok) {
    // ---- expert / m-tile resolution ----
    int y  = blockIdx.y;
    int e  = y / mtiles_per_e;
    int mt = y - e * mtiles_per_e;

    int row0 = 0;
    #pragma unroll 1
    for (int i = 0; i < e; i++) row0 += ntpe[i];
    if (row0 >= Ntok) return;
    int rows = ntpe[e];
    if (rows > Ntok - row0) rows = Ntok - row0;
    if (mt * BM >= rows) return;
    int mrows = rows - mt * BM;
    if (mrows > BM) mrows = BM;
    int row_start = row0 + mt * BM;
    int nbase     = blockIdx.x * BN;

    const float* gA = A  + (size_t)row_start * K;
    const float* gB = Bw + (size_t)e * Ncols * K + (size_t)nbase * K;

    extern __shared__ __align__(16) float smem[];
    float* bias_s = smem + STAGES * STAGE_FLOATS;

    int tid = threadIdx.x;
    for (int i = tid; i < BN; i += 512) {
        int c = nbase + i;
        bias_s[i] = (c < Ncols) ? bias[(size_t)e * Ncols + c] : 0.0f;
    }

    int KT = K / BK;   // 90

    // per-stage fill: (BM+BN)*8 = 3584 x 16B chunks, 7 per thread
    auto fill = [&](int kt) {
        float* st = smem + (kt % STAGES) * STAGE_FLOATS;
        const float* gAk = gA + kt * BK;
        const float* gBk = gB + kt * BK;
        #pragma unroll
        for (int l = 0; l < 7; l++) {
            int c = tid + 512 * l;
            if (c < BM * 8) {                       // A: 256 rows x 8 chunks
                int r  = c >> 3;
                int kv = (c & 7) * 4;
                uint32_t dst = (uint32_t)__cvta_generic_to_shared(st + r * LDT + kv);
                bool v = (r < mrows);
                cp_async16(dst, gAk + (size_t)(v ? r : 0) * K + kv, v ? 16 : 0);
            } else {                                // B: 192 rows x 8 chunks
                int c2 = c - BM * 8;
                int n  = c2 >> 3;
                int kv = (c2 & 7) * 4;
                uint32_t dst = (uint32_t)__cvta_generic_to_shared(st + A_FLOATS + n * LDT + kv);
                bool v = (nbase + n < Ncols);
                cp_async16(dst, gBk + (size_t)(v ? n : 0) * K + kv, v ? 16 : 0);
            }
        }
        cp_commit();
    };

    // warp layout: 4 (M) x 4 (N); warp tile 64x48; 4x6 m16n8 mma tiles
    int wid  = tid >> 5;
    int lane = tid & 31;
    int wm   = wid & 3;
    int wn   = wid >> 2;
    int grp  = lane >> 2;        // 0..7
    int tig  = lane & 3;         // 0..3

    float acc[4][6][4];
    #pragma unroll
    for (int i = 0; i < 4; i++)
        #pragma unroll
        for (int j = 0; j < 6; j++)
            #pragma unroll
            for (int r = 0; r < 4; r++) acc[i][j][r] = 0.0f;

    fill(0);
    if (KT > 1) fill(1); else cp_commit();

    for (int kt = 0; kt < KT; kt++) {
        if (kt + 2 < KT) fill(kt + 2);
        else             cp_commit();
        cp_wait<2>();            // oldest group (stage kt) complete
        __syncthreads();         // everyone's fills visible

        const float* sA = smem + (kt % STAGES) * STAGE_FLOATS;
        const float* sB = sA + A_FLOATS;

        #pragma unroll
        for (int s = 0; s < 4; s++) {
            int kb = s * 8;
            uint32_t bfr[6][2];
            #pragma unroll
            for (int j = 0; j < 6; j++) {
                const float* p = sB + (wn * 48 + j * 8 + grp) * LDT + kb + tig;
                bfr[j][0] = f2tf(p[0]);
                bfr[j][1] = f2tf(p[4]);
            }
            #pragma unroll
            for (int i = 0; i < 4; i++) {
                const float* p = sA + (wm * 64 + i * 16 + grp) * LDT + kb + tig;
                uint32_t afr[4];
                afr[0] = f2tf(p[0]);
                afr[1] = f2tf(p[8 * LDT]);
                afr[2] = f2tf(p[4]);
                afr[3] = f2tf(p[8 * LDT + 4]);
                #pragma unroll
                for (int j = 0; j < 6; j++)
                    mma_tf32(acc[i][j], afr, bfr[j]);
            }
        }
        __syncthreads();         // stage kt free for reuse
    }

    // ---- epilogue ----
    if (EPI == 0) {
        int Hout = Ncols >> 1;
        #pragma unroll
        for (int j = 0; j < 6; j++) {
            int lc  = wn * 48 + j * 8 + tig * 2;       // local even col
            float b0 = bias_s[lc], b1 = bias_s[lc + 1];
            int hc = (nbase + lc) >> 1;
            #pragma unroll
            for (int i = 0; i < 4; i++) {
                int m0 = wm * 64 + i * 16 + grp;
                if (m0 < mrows)
                    Cout[(size_t)(row_start + m0) * Hout + hc] =
                        swiglu_pair(acc[i][j][0] + b0, acc[i][j][1] + b1);
                if (m0 + 8 < mrows)
                    Cout[(size_t)(row_start + m0 + 8) * Hout + hc] =
                        swiglu_pair(acc[i][j][2] + b0, acc[i][j][3] + b1);
            }
        }
    } else {
        #pragma unroll
        for (int j = 0; j < 6; j++) {
            int lc  = wn * 48 + j * 8 + tig * 2;
            int col = nbase + lc;
            if (col < Ncols) {
                float b0 = bias_s[lc], b1 = bias_s[lc + 1];
                #pragma unroll
                for (int i = 0; i < 4; i++) {
                    int m0 = wm * 64 + i * 16 + grp;
                    if (m0 < mrows) {
                        float2 v = make_float2(acc[i][j][0] + b0, acc[i][j][1] + b1);
                        *(float2*)(Cout + (size_t)(row_start + m0) * Ncols + col) = v;
                    }
                    if (m0 + 8 < mrows) {
                        float2 v = make_float2(acc[i][j][2] + b0, acc[i][j][3] + b1);
                        *(float2*)(Cout + (size_t)(row_start + m0 + 8) * Ncols + col) = v;
                    }
                }
            }
        }
    }
}

// Zero padding rows (tokens >= sum(ntpe)); no-op for the equal-split inputs.
__global__ void zero_tail_kernel(float* __restrict__ out, const int* __restrict__ ntpe,
                                 int E, int Ntok, int D) {
    int total = 0;
    for (int i = 0; i < E; i++) total += ntpe[i];
    if (total >= Ntok) return;
    size_t nelem  = (size_t)(Ntok - total) * D;
    float* base   = out + (size_t)total * D;
    size_t idx    = (size_t)blockIdx.x * blockDim.x + threadIdx.x;
    size_t stride = (size_t)gridDim.x * blockDim.x;
    for (; idx < nelem; idx += stride) base[idx] = 0.0f;
}

// ---------------------------------------------------------------------------

extern "C" void kernel_launch(void* const* d_in, const int* in_sizes, int n_in,
                              void* d_out, int out_size) {
    const float* x   = (const float*)d_in[0];
    const float* w1  = (const float*)d_in[1];
    const float* b1  = (const float*)d_in[2];
    const float* w2  = (const float*)d_in[3];
    const float* b2  = (const float*)d_in[4];
    const int*   ntp = (const int*)  d_in[5];

    int E  = in_sizes[5];                 // 8
    int D  = in_sizes[4] / E;             // 2880
    int H2 = in_sizes[2] / E;             // 5760
    int H  = H2 / 2;                      // 2880
    int N  = in_sizes[0] / D;             // 16384

    float* hptr = nullptr;
    cudaGetSymbolAddress((void**)&hptr, g_h);

    cudaFuncSetAttribute((const void*)grouped_gemm_tf32<0>,
                         cudaFuncAttributeMaxDynamicSharedMemorySize, SMEM_BYTES);
    cudaFuncSetAttribute((const void*)grouped_gemm_tf32<1>,
                         cudaFuncAttributeMaxDynamicSharedMemorySize, SMEM_BYTES);

    int mtiles_per_e = (N + BM - 1) / BM;             // 64

    // GEMM1 + bias + swiglu -> g_h [N, H]
    dim3 g1((H2 + BN - 1) / BN, E * mtiles_per_e);    // (30, 512)
    grouped_gemm_tf32<0><<<g1, 512, SMEM_BYTES>>>(x, w1, b1, ntp, hptr,
                                                  /*K=*/D, /*Ncols=*/H2, E, mtiles_per_e, N);

    // GEMM2 + bias -> out [N, D]
    dim3 g2((D + BN - 1) / BN, E * mtiles_per_e);     // (15, 512)
    grouped_gemm_tf32<1><<<g2, 512, SMEM_BYTES>>>(hptr, w2, b2, ntp, (float*)d_out,
                                                  /*K=*/H, /*Ncols=*/D, E, mtiles_per_e, N);

    // zero padding rows (no-op for equal split)
    zero_tail_kernel<<<256, 256>>>((float*)d_out, ntp, E, N, D);
}